// round 4
// baseline (speedup 1.0000x reference)
#include <cuda_runtime.h>
#include <math.h>
#include <stdint.h>

// ---------------- problem constants ----------------
#define T       4096
#define HID     400
#define G4      1600          // 4*HID
#define EMB     50
#define E3      150           // 3*EMB
#define KEY     300
#define K4      1200          // 4*KEY

// rtoken: T*E3 = 614400 floats; ktoken: 400; context: T*32*HID = 52428800
#define OFF_KTOK  614400
#define OFF_CTX   614800

#define L0_CTAS 20
#define L1_CTAS 40

// ---------------- scratch (static device globals; no allocation) ----------------
__device__ float    g_xg0[(size_t)T * G4];   // precomputed input gates layer0 (+both biases)
__device__ float    g_h0[(T + 1) * HID];     // h0 timeline, slot 0 = zeros
__device__ float    g_h1[(T + 1) * HID];     // h1 timeline (== rnn_out shifted by 1)
__device__ unsigned g_flag0[(T + 1) * 32];   // per-slot, per-CTA ready flags (one line/slot)
__device__ unsigned g_flag1[(T + 1) * 64];   // layer1: 40 flags -> 64-word rows
__device__ float    g_kgate[K4];             // key lstm pre-activation gates

// ---------------- helpers ----------------
__device__ __forceinline__ float sigf(float x) {
    return __fdividef(1.f, 1.f + __expf(-x));
}
__device__ __forceinline__ float tanhf_(float x) {
    x = fminf(15.f, fmaxf(-15.f, x));
    float e = __expf(-2.f * x);
    return __fdividef(1.f - e, 1.f + e);
}
__device__ __forceinline__ float wsum(float v) {
#pragma unroll
    for (int o = 16; o > 0; o >>= 1) v += __shfl_xor_sync(0xffffffffu, v, o);
    return v;
}
__device__ __forceinline__ unsigned ld_acq(const unsigned* p) {
    unsigned v;
    asm volatile("ld.acquire.gpu.global.u32 %0, [%1];" : "=r"(v) : "l"(p) : "memory");
    return v;
}
__device__ __forceinline__ void st_rel(unsigned* p, unsigned v) {
    asm volatile("st.release.gpu.global.u32 [%0], %1;" :: "l"(p), "r"(v) : "memory");
}

// multi-value butterfly: 8 sums in 9 shfls; returns lane L holding sum(a[L&7])
__device__ __forceinline__ float reduce8(const float* a, int lane) {
    float v01 = (lane & 1) ? a[1] : a[0];
    v01 += __shfl_xor_sync(0xffffffffu, (lane & 1) ? a[0] : a[1], 1);
    float v23 = (lane & 1) ? a[3] : a[2];
    v23 += __shfl_xor_sync(0xffffffffu, (lane & 1) ? a[2] : a[3], 1);
    float v45 = (lane & 1) ? a[5] : a[4];
    v45 += __shfl_xor_sync(0xffffffffu, (lane & 1) ? a[4] : a[5], 1);
    float v67 = (lane & 1) ? a[7] : a[6];
    v67 += __shfl_xor_sync(0xffffffffu, (lane & 1) ? a[6] : a[7], 1);
    float v03 = (lane & 2) ? v23 : v01;
    v03 += __shfl_xor_sync(0xffffffffu, (lane & 2) ? v01 : v23, 2);
    float v47 = (lane & 2) ? v67 : v45;
    v47 += __shfl_xor_sync(0xffffffffu, (lane & 2) ? v45 : v67, 2);
    float v = (lane & 4) ? v47 : v03;
    v += __shfl_xor_sync(0xffffffffu, (lane & 4) ? v03 : v47, 4);
    v += __shfl_xor_sync(0xffffffffu, v, 8);
    v += __shfl_xor_sync(0xffffffffu, v, 16);
    return v;
}
// 4 sums in 6 shfls; lane L holds sum(a[L&3])
__device__ __forceinline__ float reduce4(float a0, float a1, float a2, float a3, int lane) {
    float v01 = (lane & 1) ? a1 : a0;
    v01 += __shfl_xor_sync(0xffffffffu, (lane & 1) ? a0 : a1, 1);
    float v23 = (lane & 1) ? a3 : a2;
    v23 += __shfl_xor_sync(0xffffffffu, (lane & 1) ? a2 : a3, 1);
    float v = (lane & 2) ? v23 : v01;
    v += __shfl_xor_sync(0xffffffffu, (lane & 2) ? v01 : v23, 2);
    v += __shfl_xor_sync(0xffffffffu, v, 4);
    v += __shfl_xor_sync(0xffffffffu, v, 8);
    v += __shfl_xor_sync(0xffffffffu, v, 16);
    return v;
}

// ---------------- init: flags + zero slot0 ----------------
__global__ void init_kernel() {
    int i = blockIdx.x * blockDim.x + threadIdx.x;
    if (i < (T + 1) * 32) g_flag0[i] = (i < 32) ? 1u : 0u;
    if (i < (T + 1) * 64) g_flag1[i] = (i < 64) ? 1u : 0u;
    if (i < HID) {
        g_h0[i] = 0.f;
        g_h1[i] = 0.f;
    }
}

// ---------------- kernel A: xg0 = concat-embed @ Wih0^T + bih0 + bhh0 ----------------
__global__ void __launch_bounds__(256, 1) xg0_kernel(
    const int* __restrict__ xr, const int* __restrict__ xcpc, const int* __restrict__ xma,
    const float* __restrict__ em, const float* __restrict__ ec, const float* __restrict__ er,
    const float* __restrict__ Wih0, const float* __restrict__ bih0, const float* __restrict__ bhh0)
{
    __shared__ float xs[64][53];
    __shared__ float ws[160][53];
    const int bt0 = blockIdx.x * 64;
    const int br0 = blockIdx.y * 160;
    const int tid = threadIdx.x;
    float acc[8][5];
#pragma unroll
    for (int i = 0; i < 8; i++)
#pragma unroll
        for (int r = 0; r < 5; r++) acc[i][r] = 0.f;

    for (int ch = 0; ch < 3; ch++) {
        const float* tab = (ch == 0) ? em : ((ch == 1) ? ec : er);
        const int* idx = (ch == 0) ? xma : ((ch == 1) ? xcpc : xr);
        for (int i = tid; i < 64 * 50; i += 256) {
            int tt = i / 50, kk = i - tt * 50;
            xs[tt][kk] = tab[idx[bt0 + tt] * EMB + kk];
        }
        for (int i = tid; i < 160 * 50; i += 256) {
            int rr = i / 50, kk = i - rr * 50;
            ws[rr][kk] = Wih0[(br0 + rr) * E3 + ch * 50 + kk];
        }
        __syncthreads();
        const int tr = tid & 31, tc = tid >> 5;
#pragma unroll 5
        for (int kk = 0; kk < 50; kk++) {
            float a[8], wv[5];
#pragma unroll
            for (int i = 0; i < 8; i++) a[i] = xs[tc * 8 + i][kk];
#pragma unroll
            for (int r = 0; r < 5; r++) wv[r] = ws[tr * 5 + r][kk];
#pragma unroll
            for (int i = 0; i < 8; i++)
#pragma unroll
                for (int r = 0; r < 5; r++) acc[i][r] = fmaf(a[i], wv[r], acc[i][r]);
        }
        __syncthreads();
    }
    const int tr = tid & 31, tc = tid >> 5;
#pragma unroll
    for (int r = 0; r < 5; r++) {
        int rg = br0 + tr * 5 + r;
        float bias = bih0[rg] + bhh0[rg];
#pragma unroll
        for (int i = 0; i < 8; i++) {
            int t = bt0 + tc * 8 + i;
            g_xg0[(size_t)t * G4 + rg] = acc[i][r] + bias;
        }
    }
}

// ---------------- kernel B: persistent dual-layer LSTM recurrence ----------------
// blocks 0..19:  layer0, 10 warps, each warp 2 cells (8 gate rows, K=400)
// blocks 20..59: layer1, 10 warps, each warp 1 cell  (4 gate rows, K=800: [Wih1|Whh1])
// sync: per-CTA st.release flags (one word per CTA, one 128B line per slot);
//       consumers poll the line with ld.acquire, skipping their own CTA's flag.
__global__ void __launch_bounds__(320, 1) lstm_main_kernel(
    const float* __restrict__ Whh0,
    const float* __restrict__ Wih1,
    const float* __restrict__ Whh1,
    const float* __restrict__ bih1,
    const float* __restrict__ bhh1)
{
    const int warp = threadIdx.x >> 5;
    const int lane = threadIdx.x & 31;

    if (blockIdx.x < L0_CTAS) {
        // ---------------- layer 0 ----------------
        const int cta = blockIdx.x;
        const int jbase = cta * 20 + warp * 2;
        float w[8][13];                       // [cell*4+gate][c]
#pragma unroll
        for (int jj = 0; jj < 2; jj++)
#pragma unroll
            for (int g = 0; g < 4; g++)
#pragma unroll
                for (int c = 0; c < 13; c++) {
                    int k = lane + 32 * c;
                    w[jj * 4 + g][c] = (k < HID) ? Whh0[(size_t)(jbase + jj + g * 400) * HID + k] : 0.f;
                }
        float cst = 0.f;                      // live in lanes 0,1 (their cell's state)

        for (int t = 0; t < T; t++) {
            // lanes 0,1 prefetch their cell's 4 xg values (independent of h -> overlaps poll)
            float x0 = 0.f, x1 = 0.f, x2 = 0.f, x3 = 0.f;
            if (lane < 2) {
                const float* xg = g_xg0 + (size_t)t * G4 + jbase + lane;
                x0 = __ldg(xg); x1 = __ldg(xg + 400); x2 = __ldg(xg + 800); x3 = __ldg(xg + 1200);
            }
            // wait for h0[t] from the OTHER 19 CTAs (own data is L2-visible post-bar)
            const unsigned* fl = g_flag0 + (size_t)t * 32;
            for (;;) {
                unsigned ok = (lane < 20 && lane != cta) ? ld_acq(fl + lane) : 1u;
                if (__all_sync(0xffffffffu, ok != 0u)) break;
            }
            // read h (coalesced, L2-homed)
            const float* hb = g_h0 + (size_t)t * HID;
            float hv[13];
#pragma unroll
            for (int c = 0; c < 13; c++) {
                int k = lane + 32 * c;
                hv[c] = (k < HID) ? __ldcg(hb + k) : 0.f;
            }
            float a[8];
#pragma unroll
            for (int r = 0; r < 8; r++) a[r] = 0.f;
#pragma unroll
            for (int c = 0; c < 13; c++)
#pragma unroll
                for (int r = 0; r < 8; r++) a[r] = fmaf(w[r][c], hv[c], a[r]);
            // lane L now gets sum(a[L&7]); gather cell gates: lane0 <- 0..3, lane1 <- 4..7
            float v = reduce8(a, lane);
            float g0 = __shfl_sync(0xffffffffu, v, (lane << 2) & 31);
            float g1 = __shfl_sync(0xffffffffu, v, ((lane << 2) + 1) & 31);
            float g2 = __shfl_sync(0xffffffffu, v, ((lane << 2) + 2) & 31);
            float g3 = __shfl_sync(0xffffffffu, v, ((lane << 2) + 3) & 31);
            if (lane < 2) {
                float gi = sigf(g0 + x0);
                float gf = sigf(g1 + x1);
                float gg = tanhf_(g2 + x2);
                float go = sigf(g3 + x3);
                cst = gf * cst + gi * gg;
                float h = go * tanhf_(cst);
                __stcg(g_h0 + (size_t)(t + 1) * HID + jbase + lane, h);
            }
            __syncthreads();
            if (threadIdx.x == 0) st_rel(g_flag0 + (size_t)(t + 1) * 32 + cta, 1u);
        }
    } else {
        // ---------------- layer 1 ----------------
        const int cta = blockIdx.x - L0_CTAS;
        const int j = cta * 10 + warp;
        float w[4][25];
#pragma unroll
        for (int g = 0; g < 4; g++)
#pragma unroll
            for (int c = 0; c < 25; c++) {
                int k = lane + 32 * c;
                int row = j + g * 400;
                w[g][c] = (k < HID) ? Wih1[(size_t)row * HID + k]
                                    : Whh1[(size_t)row * HID + (k - HID)];
            }
        float b0 = 0.f, b1 = 0.f, b2 = 0.f, b3 = 0.f, cst = 0.f;
        if (lane == 0) {
            b0 = bih1[j] + bhh1[j];
            b1 = bih1[j + 400] + bhh1[j + 400];
            b2 = bih1[j + 800] + bhh1[j + 800];
            b3 = bih1[j + 1200] + bhh1[j + 1200];
        }

        for (int t = 0; t < T; t++) {
            // fused poll: h0[t] (slot t+1, 20 flags) AND h1[t-1] (slot t, 40 flags)
            const unsigned* f0 = g_flag0 + (size_t)(t + 1) * 32;
            const unsigned* f1 = g_flag1 + (size_t)t * 64;
            for (;;) {
                unsigned okA = (lane < 20) ? ld_acq(f0 + lane) : 1u;
                unsigned okB = (lane == cta) ? 1u : ld_acq(f1 + lane);
                unsigned okC = (lane < 8) ? ((lane + 32 == cta) ? 1u : ld_acq(f1 + 32 + lane)) : 1u;
                if (__all_sync(0xffffffffu, (okA != 0u) & (okB != 0u) & (okC != 0u))) break;
            }
            const float* h0b = g_h0 + (size_t)(t + 1) * HID;
            const float* h1b = g_h1 + (size_t)t * HID;
            float hv[25];
#pragma unroll
            for (int c = 0; c < 25; c++) {
                int k = lane + 32 * c;
                hv[c] = __ldcg((k < HID) ? (h0b + k) : (h1b + (k - HID)));
            }
            float a0 = 0.f, a1 = 0.f, a2 = 0.f, a3 = 0.f;
#pragma unroll
            for (int c = 0; c < 25; c++) {
                a0 = fmaf(w[0][c], hv[c], a0);
                a1 = fmaf(w[1][c], hv[c], a1);
                a2 = fmaf(w[2][c], hv[c], a2);
                a3 = fmaf(w[3][c], hv[c], a3);
            }
            // lane L gets sum(a[L&3]); gather all 4 to lane0
            float v = reduce4(a0, a1, a2, a3, lane);
            float g0 = __shfl_sync(0xffffffffu, v, 0);
            float g1 = __shfl_sync(0xffffffffu, v, 1);
            float g2 = __shfl_sync(0xffffffffu, v, 2);
            float g3 = __shfl_sync(0xffffffffu, v, 3);
            if (lane == 0) {
                float gi = sigf(g0 + b0);
                float gf = sigf(g1 + b1);
                float gg = tanhf_(g2 + b2);
                float go = sigf(g3 + b3);
                cst = gf * cst + gi * gg;
                float h = go * tanhf_(cst);
                __stcg(g_h1 + (size_t)(t + 1) * HID + j, h);
            }
            __syncthreads();
            if (threadIdx.x == 0) st_rel(g_flag1 + (size_t)(t + 1) * 64 + cta, 1u);
        }
    }
}

// ---------------- kernel C: rtoken = rnn_out @ fcW^T + fcb ----------------
__global__ void __launch_bounds__(256, 1) rtoken_kernel(
    const float* __restrict__ fcW, const float* __restrict__ fcb, float* __restrict__ out)
{
    __shared__ float xs[64][53];
    __shared__ float ws[160][53];
    const int bt0 = blockIdx.x * 64;
    const int tid = threadIdx.x;
    float acc[8][5];
#pragma unroll
    for (int i = 0; i < 8; i++)
#pragma unroll
        for (int r = 0; r < 5; r++) acc[i][r] = 0.f;

    for (int ch = 0; ch < 8; ch++) {
        int k0 = ch * 50;
        for (int i = tid; i < 64 * 50; i += 256) {
            int tt = i / 50, kk = i - tt * 50;
            xs[tt][kk] = g_h1[(size_t)(bt0 + tt + 1) * HID + k0 + kk];
        }
        for (int i = tid; i < 160 * 50; i += 256) {
            int rr = i / 50, kk = i - rr * 50;
            ws[rr][kk] = (rr < E3) ? fcW[rr * HID + k0 + kk] : 0.f;
        }
        __syncthreads();
        const int tr = tid & 31, tc = tid >> 5;
#pragma unroll 5
        for (int kk = 0; kk < 50; kk++) {
            float a[8], wv[5];
#pragma unroll
            for (int i = 0; i < 8; i++) a[i] = xs[tc * 8 + i][kk];
#pragma unroll
            for (int r = 0; r < 5; r++) wv[r] = ws[tr * 5 + r][kk];
#pragma unroll
            for (int i = 0; i < 8; i++)
#pragma unroll
                for (int r = 0; r < 5; r++) acc[i][r] = fmaf(a[i], wv[r], acc[i][r]);
        }
        __syncthreads();
    }
    const int tr = tid & 31, tc = tid >> 5;
#pragma unroll
    for (int r = 0; r < 5; r++) {
        int rg = tr * 5 + r;
        if (rg < E3) {
            float bias = fcb[rg];
#pragma unroll
            for (int i = 0; i < 8; i++) {
                int t = bt0 + tc * 8 + i;
                out[(size_t)t * E3 + rg] = acc[i][r] + bias;
            }
        }
    }
}

// ---------------- kernel D: context fill ----------------
__global__ void __launch_bounds__(128, 1) ctx_kernel(
    const float* __restrict__ actW, const float* __restrict__ actb,
    const float* __restrict__ Dp, float* __restrict__ out)
{
    const int t = blockIdx.x;
    const int warp = threadIdx.x >> 5, lane = threadIdx.x & 31;
    __shared__ float red[4];
    const float* hr = g_h1 + (size_t)(t + 1) * HID;
    const float* wrow = (warp < 3) ? (actW + warp * HID) : Dp;
    float acc = 0.f;
#pragma unroll
    for (int c = 0; c < 13; c++) {
        int k = lane + 32 * c;
        if (k < HID) acc = fmaf(__ldg(wrow + k), __ldg(hr + k), acc);
    }
    acc = wsum(acc);
    if (lane == 0) red[warp] = acc + ((warp < 3) ? actb[warp] : 0.f);
    __syncthreads();
    float l0 = red[0], l1 = red[1], l2 = red[2], d = red[3];
    float m = fmaxf(l0, fmaxf(l1, l2));
    float e0 = __expf(l0 - m), e1 = __expf(l1 - m), e2 = __expf(l2 - m);
    float p0 = __fdividef(e0, e0 + e1 + e2);
    float v = p0 * sigf(d);

    float4* dst = (float4*)(out + OFF_CTX + (size_t)t * 32 * HID);
    float4 vz = make_float4(v, v, v, v);
    float4 z = make_float4(0.f, 0.f, 0.f, 0.f);
    for (int q = threadIdx.x; q < 3200; q += 128) {
        __stcs(dst + q, (q < 100) ? vz : z);
    }
}

// ---------------- kernel E1: key lstm gates ----------------
__global__ void __launch_bounds__(128, 1) keygate_kernel(
    const float* __restrict__ kWih, const float* __restrict__ kbih, const float* __restrict__ kbhh)
{
    const int gw = blockIdx.x * 4 + (threadIdx.x >> 5);
    const int lane = threadIdx.x & 31;
    const float* hr = g_h1 + (size_t)T * HID;
    float hv[13];
#pragma unroll
    for (int c = 0; c < 13; c++) {
        int k = lane + 32 * c;
        hv[c] = (k < HID) ? __ldg(hr + k) : 0.f;
    }
    for (int rr = 0; rr < 30; rr++) {
        int r = gw * 30 + rr;
        float acc = 0.f;
#pragma unroll
        for (int c = 0; c < 13; c++) {
            int k = lane + 32 * c;
            if (k < HID) acc = fmaf(__ldg(kWih + (size_t)r * HID + k), hv[c], acc);
        }
        acc = wsum(acc);
        if (lane == 0) g_kgate[r] = acc + kbih[r] + kbhh[r];
    }
}

// ---------------- kernel E2: kh nonlinearity + ktoken ----------------
__global__ void __launch_bounds__(512, 1) keyout_kernel(
    const float* __restrict__ kfcW, const float* __restrict__ kfcb, float* __restrict__ out)
{
    __shared__ float kh[KEY];
    const int tid = threadIdx.x;
    if (tid < KEY) {
        float gi = g_kgate[tid], gg = g_kgate[600 + tid], go = g_kgate[900 + tid];
        float c = sigf(gi) * tanhf_(gg);
        kh[tid] = sigf(go) * tanhf_(c);
    }
    __syncthreads();
    const int warp = tid >> 5, lane = tid & 31;
    for (int rr = 0; rr < 25; rr++) {
        int r = warp * 25 + rr;
        float acc = 0.f;
#pragma unroll
        for (int c = 0; c < 10; c++) {
            int k = lane + 32 * c;
            if (k < KEY) acc = fmaf(__ldg(kfcW + (size_t)r * KEY + k), kh[k], acc);
        }
        acc = wsum(acc);
        if (lane == 0) out[OFF_KTOK + r] = acc + kfcb[r];
    }
}

// ---------------- launch ----------------
extern "C" void kernel_launch(void* const* d_in, const int* in_sizes, int n_in,
                              void* d_out, int out_size)
{
    const int*   xr       = (const int*)d_in[0];
    const int*   xcpc     = (const int*)d_in[1];
    const int*   xma      = (const int*)d_in[2];
    const float* em       = (const float*)d_in[3];
    const float* ec       = (const float*)d_in[4];
    const float* er       = (const float*)d_in[5];
    const float* Wih0     = (const float*)d_in[6];
    const float* Whh0     = (const float*)d_in[7];
    const float* bih0     = (const float*)d_in[8];
    const float* bhh0     = (const float*)d_in[9];
    const float* Wih1     = (const float*)d_in[10];
    const float* Whh1     = (const float*)d_in[11];
    const float* bih1     = (const float*)d_in[12];
    const float* bhh1     = (const float*)d_in[13];
    const float* fcW      = (const float*)d_in[14];
    const float* fcb      = (const float*)d_in[15];
    const float* actW     = (const float*)d_in[16];
    const float* actb     = (const float*)d_in[17];
    const float* Dp       = (const float*)d_in[18];
    const float* kWih     = (const float*)d_in[19];
    const float* kbih     = (const float*)d_in[21];
    const float* kbhh     = (const float*)d_in[22];
    const float* kfcW     = (const float*)d_in[23];
    const float* kfcb     = (const float*)d_in[24];
    float* out = (float*)d_out;

    init_kernel<<<((T + 1) * 64 + 255) / 256, 256>>>();
    xg0_kernel<<<dim3(T / 64, G4 / 160), 256>>>(xr, xcpc, xma, em, ec, er, Wih0, bih0, bhh0);
    lstm_main_kernel<<<L0_CTAS + L1_CTAS, 320>>>(Whh0, Wih1, Whh1, bih1, bhh1);
    rtoken_kernel<<<T / 64, 256>>>(fcW, fcb, out);
    ctx_kernel<<<T, 128>>>(actW, actb, Dp, out);
    keygate_kernel<<<10, 128>>>(kWih, kbih, kbhh);
    keyout_kernel<<<1, 512>>>(kfcW, kfcb, out);
}

// round 6
// speedup vs baseline: 1.8392x; 1.8392x over previous
#include <cuda_runtime.h>
#include <math.h>
#include <stdint.h>

// ---------------- problem constants ----------------
#define T       4096
#define HID     400
#define G4      1600          // 4*HID
#define EMB     50
#define E3      150           // 3*EMB
#define KEY     300
#define K4      1200          // 4*KEY

// rtoken: T*E3 = 614400 floats; ktoken: 400; context: T*32*HID = 52428800
#define OFF_KTOK  614400
#define OFF_CTX   614800

#define NCTA_GRP 20           // CTAs per group (L0 / L1-critical / L1-helper)

// ---------------- scratch (static device globals; no allocation) ----------------
__device__ float    g_xg0[(size_t)T * G4];   // layer0 input gates (+both biases)
__device__ float    g_u[(size_t)T * G4];     // layer1 input gates u[t]=Wih1*h0[t]+biases
__device__ float    g_h0[(T + 1) * HID];     // h0 timeline, slot 0 = zeros
__device__ float    g_h1[(T + 1) * HID];     // h1 timeline (rnn_out shifted by 1)
__device__ unsigned g_cnt0[(T + 1) * 32];    // h0 slot-ready counters (one 128B line each)
__device__ unsigned g_cnt1[(T + 1) * 32];    // h1 slot-ready counters
__device__ unsigned g_cntu[(T + 1) * 32];    // u[t]-ready counters
__device__ float    g_kgate[K4];             // key lstm pre-activation gates

// ---------------- helpers ----------------
__device__ __forceinline__ float sigf(float x) {
    return __fdividef(1.f, 1.f + __expf(-x));
}
__device__ __forceinline__ float tanhf_(float x) {
    x = fminf(15.f, fmaxf(-15.f, x));
    float e = __expf(-2.f * x);
    return __fdividef(1.f - e, 1.f + e);
}
__device__ __forceinline__ float wsum(float v) {
#pragma unroll
    for (int o = 16; o > 0; o >>= 1) v += __shfl_xor_sync(0xffffffffu, v, o);
    return v;
}
__device__ __forceinline__ unsigned ld_acq(const unsigned* p) {
    unsigned v;
    asm volatile("ld.acquire.gpu.global.u32 %0, [%1];" : "=r"(v) : "l"(p) : "memory");
    return v;
}
__device__ __forceinline__ void red_rel(unsigned* p) {
    asm volatile("red.release.gpu.global.add.u32 [%0], %1;" :: "l"(p), "r"(1u) : "memory");
}

// multi-value butterfly: 8 sums in 9 shfls; lane L ends with sum(a[L&7])
__device__ __forceinline__ float reduce8(const float* a, int lane) {
    float v01 = (lane & 1) ? a[1] : a[0];
    v01 += __shfl_xor_sync(0xffffffffu, (lane & 1) ? a[0] : a[1], 1);
    float v23 = (lane & 1) ? a[3] : a[2];
    v23 += __shfl_xor_sync(0xffffffffu, (lane & 1) ? a[2] : a[3], 1);
    float v45 = (lane & 1) ? a[5] : a[4];
    v45 += __shfl_xor_sync(0xffffffffu, (lane & 1) ? a[4] : a[5], 1);
    float v67 = (lane & 1) ? a[7] : a[6];
    v67 += __shfl_xor_sync(0xffffffffu, (lane & 1) ? a[6] : a[7], 1);
    float v03 = (lane & 2) ? v23 : v01;
    v03 += __shfl_xor_sync(0xffffffffu, (lane & 2) ? v01 : v23, 2);
    float v47 = (lane & 2) ? v67 : v45;
    v47 += __shfl_xor_sync(0xffffffffu, (lane & 2) ? v45 : v67, 2);
    float v = (lane & 4) ? v47 : v03;
    v += __shfl_xor_sync(0xffffffffu, (lane & 4) ? v03 : v47, 4);
    v += __shfl_xor_sync(0xffffffffu, v, 8);
    v += __shfl_xor_sync(0xffffffffu, v, 16);
    return v;
}

// ---------------- init: counters + zero h slot0 ----------------
__global__ void init_kernel() {
    int i = blockIdx.x * blockDim.x + threadIdx.x;
    if (i < (T + 1) * 32) {
        unsigned seed = (i == 0) ? NCTA_GRP : 0u;
        g_cnt0[i] = seed;
        g_cnt1[i] = seed;
        g_cntu[i] = 0u;
    }
    if (i < HID) { g_h0[i] = 0.f; g_h1[i] = 0.f; }
}

// ---------------- kernel A: xg0 = concat-embed @ Wih0^T + bih0 + bhh0 ----------------
__global__ void __launch_bounds__(256, 1) xg0_kernel(
    const int* __restrict__ xr, const int* __restrict__ xcpc, const int* __restrict__ xma,
    const float* __restrict__ em, const float* __restrict__ ec, const float* __restrict__ er,
    const float* __restrict__ Wih0, const float* __restrict__ bih0, const float* __restrict__ bhh0)
{
    __shared__ float xs[64][53];
    __shared__ float ws[160][53];
    const int bt0 = blockIdx.x * 64;
    const int br0 = blockIdx.y * 160;
    const int tid = threadIdx.x;
    float acc[8][5];
#pragma unroll
    for (int i = 0; i < 8; i++)
#pragma unroll
        for (int r = 0; r < 5; r++) acc[i][r] = 0.f;

    for (int ch = 0; ch < 3; ch++) {
        const float* tab = (ch == 0) ? em : ((ch == 1) ? ec : er);
        const int* idx = (ch == 0) ? xma : ((ch == 1) ? xcpc : xr);
        for (int i = tid; i < 64 * 50; i += 256) {
            int tt = i / 50, kk = i - tt * 50;
            xs[tt][kk] = tab[idx[bt0 + tt] * EMB + kk];
        }
        for (int i = tid; i < 160 * 50; i += 256) {
            int rr = i / 50, kk = i - rr * 50;
            ws[rr][kk] = Wih0[(br0 + rr) * E3 + ch * 50 + kk];
        }
        __syncthreads();
        const int tr = tid & 31, tc = tid >> 5;
#pragma unroll 5
        for (int kk = 0; kk < 50; kk++) {
            float a[8], wv[5];
#pragma unroll
            for (int i = 0; i < 8; i++) a[i] = xs[tc * 8 + i][kk];
#pragma unroll
            for (int r = 0; r < 5; r++) wv[r] = ws[tr * 5 + r][kk];
#pragma unroll
            for (int i = 0; i < 8; i++)
#pragma unroll
                for (int r = 0; r < 5; r++) acc[i][r] = fmaf(a[i], wv[r], acc[i][r]);
        }
        __syncthreads();
    }
    const int tr = tid & 31, tc = tid >> 5;
#pragma unroll
    for (int r = 0; r < 5; r++) {
        int rg = br0 + tr * 5 + r;
        float bias = bih0[rg] + bhh0[rg];
#pragma unroll
        for (int i = 0; i < 8; i++) {
            int t = bt0 + tc * 8 + i;
            g_xg0[(size_t)t * G4 + rg] = acc[i][r] + bias;
        }
    }
}

// ---------------- kernel B: persistent recurrence ----------------
// blocks  0..19: layer0 critical loop  (Whh0 * h0[t-1], K=400, 2 cells/warp)
// blocks 20..39: layer1 critical loop  (Whh1 * h1[t-1], K=400; u[t] via cnt_u counter)
// blocks 40..59: layer1 helper         (u[t] = Wih1 * h0[t] + biases)
// all cross-CTA sync = proven pattern: weak stores -> CTA barrier -> thread0 red.release;
// consumers: single uniform ld.acquire counter word per poll.
__global__ void __launch_bounds__(320, 1) lstm_main_kernel(
    const float* __restrict__ Whh0,
    const float* __restrict__ Wih1,
    const float* __restrict__ Whh1,
    const float* __restrict__ bih1,
    const float* __restrict__ bhh1)
{
    const int warp = threadIdx.x >> 5;
    const int lane = threadIdx.x & 31;
    const int grp  = blockIdx.x / NCTA_GRP;       // 0=L0, 1=L1crit, 2=helper
    const int cta  = blockIdx.x % NCTA_GRP;
    const int jbase = cta * 20 + warp * 2;        // first of this warp's 2 cells

    if (grp == 2) {
        // ---------------- layer-1 helper: u[t] = Wih1 * h0[t] + (bih1+bhh1) ----------------
        float w[8][13];
#pragma unroll
        for (int jj = 0; jj < 2; jj++)
#pragma unroll
            for (int g = 0; g < 4; g++)
#pragma unroll
                for (int c = 0; c < 13; c++) {
                    int k = lane + 32 * c;
                    w[jj * 4 + g][c] = (k < HID) ? Wih1[(size_t)(jbase + jj + g * 400) * HID + k] : 0.f;
                }
        float bias = 0.f;
        int doff = 0;
        if (lane < 8) {
            int cell = jbase + (lane >> 2);       // lanes 0-3: cell jbase; 4-7: jbase+1
            int gt = lane & 3;
            bias = bih1[gt * 400 + cell] + bhh1[gt * 400 + cell];
            doff = gt * 400 + cell;
        }
        for (int t = 0; t < T; t++) {
            const unsigned* cp = g_cnt0 + (size_t)(t + 1) * 32;   // h0[t] lives in slot t+1
            while (ld_acq(cp) < NCTA_GRP) {}
            const float* hb = g_h0 + (size_t)(t + 1) * HID;
            float hv[13];
#pragma unroll
            for (int c = 0; c < 13; c++) {
                int k = lane + 32 * c;
                hv[c] = (k < HID) ? __ldcg(hb + k) : 0.f;
            }
            float a[8];
#pragma unroll
            for (int r = 0; r < 8; r++) a[r] = 0.f;
#pragma unroll
            for (int c = 0; c < 13; c++)
#pragma unroll
                for (int r = 0; r < 8; r++) a[r] = fmaf(w[r][c], hv[c], a[r]);
            float v = reduce8(a, lane);
            if (lane < 8) __stcg(g_u + (size_t)t * G4 + doff, v + bias);
            __syncthreads();                       // all warps' u stores done
            if (threadIdx.x == 0) red_rel(g_cntu + (size_t)t * 32);
        }
        return;
    }

    // ---------------- critical loops (L0 and L1) — identical shape ----------------
    const float* Whh = (grp == 0) ? Whh0 : Whh1;
    float* hbuf       = (grp == 0) ? g_h0 : g_h1;
    unsigned* cnt     = (grp == 0) ? g_cnt0 : g_cnt1;

    float w[8][13];
#pragma unroll
    for (int jj = 0; jj < 2; jj++)
#pragma unroll
        for (int g = 0; g < 4; g++)
#pragma unroll
            for (int c = 0; c < 13; c++) {
                int k = lane + 32 * c;
                w[jj * 4 + g][c] = (k < HID) ? Whh[(size_t)(jbase + jj + g * 400) * HID + k] : 0.f;
            }
    __shared__ float gbuf[2][10][8];
    const int cell = cta * 20 + lane;             // warp0 lanes<20 = cell lanes
    float cst = 0.f;

    for (int t = 0; t < T; t++) {
        float x0 = 0.f, x1 = 0.f, x2 = 0.f, x3 = 0.f;
        if (grp == 0 && warp == 0 && lane < 20) {
            // xg0 precomputed: prefetch before poll (off critical path)
            const float* xg = g_xg0 + (size_t)t * G4 + cell;
            x0 = __ldg(xg); x1 = __ldg(xg + 400); x2 = __ldg(xg + 800); x3 = __ldg(xg + 1200);
        }
        // uniform single-word counter polls
        {
            const unsigned* cp = cnt + (size_t)t * 32;
            while (ld_acq(cp) < NCTA_GRP) {}
        }
        if (grp == 1) {
            const unsigned* cu = g_cntu + (size_t)t * 32;
            while (ld_acq(cu) < NCTA_GRP) {}
            if (warp == 0 && lane < 20) {
                const float* up = g_u + (size_t)t * G4 + cell;
                x0 = __ldcg(up);       x1 = __ldcg(up + 400);
                x2 = __ldcg(up + 800); x3 = __ldcg(up + 1200);
            }
        }
        const float* hb = hbuf + (size_t)t * HID;
        float hv[13];
#pragma unroll
        for (int c = 0; c < 13; c++) {
            int k = lane + 32 * c;
            hv[c] = (k < HID) ? __ldcg(hb + k) : 0.f;
        }
        float a[8];
#pragma unroll
        for (int r = 0; r < 8; r++) a[r] = 0.f;
#pragma unroll
        for (int c = 0; c < 13; c++)
#pragma unroll
            for (int r = 0; r < 8; r++) a[r] = fmaf(w[r][c], hv[c], a[r]);
        float v = reduce8(a, lane);               // lane L holds sum(a[L&7])
        if (lane < 8) gbuf[t & 1][warp][lane] = v;
        __syncthreads();
        if (warp == 0) {
            if (lane < 20) {
                int sw = lane >> 1, jj = lane & 1;
                float gi = sigf(gbuf[t & 1][sw][jj * 4 + 0] + x0);
                float gf = sigf(gbuf[t & 1][sw][jj * 4 + 1] + x1);
                float gg = tanhf_(gbuf[t & 1][sw][jj * 4 + 2] + x2);
                float go = sigf(gbuf[t & 1][sw][jj * 4 + 3] + x3);
                cst = gf * cst + gi * gg;
                float h = go * tanhf_(cst);
                __stcg(hbuf + (size_t)(t + 1) * HID + cell, h);
            }
            __syncwarp();
            if (lane == 0) red_rel(cnt + (size_t)(t + 1) * 32);
        }
    }
}

// ---------------- kernel C: rtoken = rnn_out @ fcW^T + fcb ----------------
__global__ void __launch_bounds__(256, 1) rtoken_kernel(
    const float* __restrict__ fcW, const float* __restrict__ fcb, float* __restrict__ out)
{
    __shared__ float xs[64][53];
    __shared__ float ws[160][53];
    const int bt0 = blockIdx.x * 64;
    const int tid = threadIdx.x;
    float acc[8][5];
#pragma unroll
    for (int i = 0; i < 8; i++)
#pragma unroll
        for (int r = 0; r < 5; r++) acc[i][r] = 0.f;

    for (int ch = 0; ch < 8; ch++) {
        int k0 = ch * 50;
        for (int i = tid; i < 64 * 50; i += 256) {
            int tt = i / 50, kk = i - tt * 50;
            xs[tt][kk] = g_h1[(size_t)(bt0 + tt + 1) * HID + k0 + kk];
        }
        for (int i = tid; i < 160 * 50; i += 256) {
            int rr = i / 50, kk = i - rr * 50;
            ws[rr][kk] = (rr < E3) ? fcW[rr * HID + k0 + kk] : 0.f;
        }
        __syncthreads();
        const int tr = tid & 31, tc = tid >> 5;
#pragma unroll 5
        for (int kk = 0; kk < 50; kk++) {
            float a[8], wv[5];
#pragma unroll
            for (int i = 0; i < 8; i++) a[i] = xs[tc * 8 + i][kk];
#pragma unroll
            for (int r = 0; r < 5; r++) wv[r] = ws[tr * 5 + r][kk];
#pragma unroll
            for (int i = 0; i < 8; i++)
#pragma unroll
                for (int r = 0; r < 5; r++) acc[i][r] = fmaf(a[i], wv[r], acc[i][r]);
        }
        __syncthreads();
    }
    const int tr = tid & 31, tc = tid >> 5;
#pragma unroll
    for (int r = 0; r < 5; r++) {
        int rg = tr * 5 + r;
        if (rg < E3) {
            float bias = fcb[rg];
#pragma unroll
            for (int i = 0; i < 8; i++) {
                int t = bt0 + tc * 8 + i;
                out[(size_t)t * E3 + rg] = acc[i][r] + bias;
            }
        }
    }
}

// ---------------- kernel D: context fill ----------------
__global__ void __launch_bounds__(128, 1) ctx_kernel(
    const float* __restrict__ actW, const float* __restrict__ actb,
    const float* __restrict__ Dp, float* __restrict__ out)
{
    const int t = blockIdx.x;
    const int warp = threadIdx.x >> 5, lane = threadIdx.x & 31;
    __shared__ float red[4];
    const float* hr = g_h1 + (size_t)(t + 1) * HID;
    const float* wrow = (warp < 3) ? (actW + warp * HID) : Dp;
    float acc = 0.f;
#pragma unroll
    for (int c = 0; c < 13; c++) {
        int k = lane + 32 * c;
        if (k < HID) acc = fmaf(__ldg(wrow + k), __ldg(hr + k), acc);
    }
    acc = wsum(acc);
    if (lane == 0) red[warp] = acc + ((warp < 3) ? actb[warp] : 0.f);
    __syncthreads();
    float l0 = red[0], l1 = red[1], l2 = red[2], d = red[3];
    float m = fmaxf(l0, fmaxf(l1, l2));
    float e0 = __expf(l0 - m), e1 = __expf(l1 - m), e2 = __expf(l2 - m);
    float p0 = __fdividef(e0, e0 + e1 + e2);
    float v = p0 * sigf(d);

    float4* dst = (float4*)(out + OFF_CTX + (size_t)t * 32 * HID);
    float4 vz = make_float4(v, v, v, v);
    float4 z = make_float4(0.f, 0.f, 0.f, 0.f);
    for (int q = threadIdx.x; q < 3200; q += 128) {
        __stcs(dst + q, (q < 100) ? vz : z);
    }
}

// ---------------- kernel E1: key lstm gates ----------------
__global__ void __launch_bounds__(128, 1) keygate_kernel(
    const float* __restrict__ kWih, const float* __restrict__ kbih, const float* __restrict__ kbhh)
{
    const int gw = blockIdx.x * 4 + (threadIdx.x >> 5);
    const int lane = threadIdx.x & 31;
    const float* hr = g_h1 + (size_t)T * HID;
    float hv[13];
#pragma unroll
    for (int c = 0; c < 13; c++) {
        int k = lane + 32 * c;
        hv[c] = (k < HID) ? __ldg(hr + k) : 0.f;
    }
    for (int rr = 0; rr < 30; rr++) {
        int r = gw * 30 + rr;
        float acc = 0.f;
#pragma unroll
        for (int c = 0; c < 13; c++) {
            int k = lane + 32 * c;
            if (k < HID) acc = fmaf(__ldg(kWih + (size_t)r * HID + k), hv[c], acc);
        }
        acc = wsum(acc);
        if (lane == 0) g_kgate[r] = acc + kbih[r] + kbhh[r];
    }
}

// ---------------- kernel E2: kh nonlinearity + ktoken ----------------
__global__ void __launch_bounds__(512, 1) keyout_kernel(
    const float* __restrict__ kfcW, const float* __restrict__ kfcb, float* __restrict__ out)
{
    __shared__ float kh[KEY];
    const int tid = threadIdx.x;
    if (tid < KEY) {
        float gi = g_kgate[tid], gg = g_kgate[600 + tid], go = g_kgate[900 + tid];
        float c = sigf(gi) * tanhf_(gg);
        kh[tid] = sigf(go) * tanhf_(c);
    }
    __syncthreads();
    const int warp = tid >> 5, lane = tid & 31;
    for (int rr = 0; rr < 25; rr++) {
        int r = warp * 25 + rr;
        float acc = 0.f;
#pragma unroll
        for (int c = 0; c < 10; c++) {
            int k = lane + 32 * c;
            if (k < KEY) acc = fmaf(__ldg(kfcW + (size_t)r * KEY + k), kh[k], acc);
        }
        acc = wsum(acc);
        if (lane == 0) out[OFF_KTOK + r] = acc + kfcb[r];
    }
}

// ---------------- launch ----------------
extern "C" void kernel_launch(void* const* d_in, const int* in_sizes, int n_in,
                              void* d_out, int out_size)
{
    const int*   xr       = (const int*)d_in[0];
    const int*   xcpc     = (const int*)d_in[1];
    const int*   xma      = (const int*)d_in[2];
    const float* em       = (const float*)d_in[3];
    const float* ec       = (const float*)d_in[4];
    const float* er       = (const float*)d_in[5];
    const float* Wih0     = (const float*)d_in[6];
    const float* Whh0     = (const float*)d_in[7];
    const float* bih0     = (const float*)d_in[8];
    const float* bhh0     = (const float*)d_in[9];
    const float* Wih1     = (const float*)d_in[10];
    const float* Whh1     = (const float*)d_in[11];
    const float* bih1     = (const float*)d_in[12];
    const float* bhh1     = (const float*)d_in[13];
    const float* fcW      = (const float*)d_in[14];
    const float* fcb      = (const float*)d_in[15];
    const float* actW     = (const float*)d_in[16];
    const float* actb     = (const float*)d_in[17];
    const float* Dp       = (const float*)d_in[18];
    const float* kWih     = (const float*)d_in[19];
    const float* kbih     = (const float*)d_in[21];
    const float* kbhh     = (const float*)d_in[22];
    const float* kfcW     = (const float*)d_in[23];
    const float* kfcb     = (const float*)d_in[24];
    float* out = (float*)d_out;

    init_kernel<<<((T + 1) * 32 + 255) / 256, 256>>>();
    xg0_kernel<<<dim3(T / 64, G4 / 160), 256>>>(xr, xcpc, xma, em, ec, er, Wih0, bih0, bhh0);
    lstm_main_kernel<<<3 * NCTA_GRP, 320>>>(Whh0, Wih1, Whh1, bih1, bhh1);
    rtoken_kernel<<<T / 64, 256>>>(fcW, fcb, out);
    ctx_kernel<<<T, 128>>>(actW, actb, Dp, out);
    keygate_kernel<<<10, 128>>>(kWih, kbih, kbhh);
    keyout_kernel<<<1, 512>>>(kfcW, kfcb, out);
}

// round 8
// speedup vs baseline: 2.0576x; 1.1187x over previous
#include <cuda_runtime.h>
#include <math.h>
#include <stdint.h>

// ---------------- problem constants ----------------
#define T       4096
#define HID     400
#define HIDP    416           // padded h buffer (zeros in pad)
#define G4      1600          // 4*HID
#define EMB     50
#define E3      150           // 3*EMB
#define KEY     300
#define K4      1200          // 4*KEY

// rtoken: T*E3 = 614400 floats; ktoken: 400; context: T*32*HID = 52428800
#define OFF_KTOK  614400
#define OFF_CTX   614800

#define CL      16            // cluster size (CTAs per recurrence group)
#define CELLS   25            // cells per CTA (16*25 = 400)
#define ROWS    100           // gate rows per CTA
#define RPW     10            // rows per warp
#define THREADS 320

// ---------------- scratch (static device globals; no allocation) ----------------
__device__ float    g_xg0[(size_t)T * G4];   // layer0 input gates (+both biases)
__device__ float    g_u[(size_t)T * G4];     // layer1 input gates u[t]=Wih1*h0[t]+biases
__device__ float    g_h0[(T + 1) * HID];     // h0 timeline (global copy for helpers)
__device__ float    g_h1[(T + 1) * HID];     // h1 timeline (for rtoken/ctx/key)
__device__ unsigned g_cnt0[(T + 1) * 32];    // h0 slot-ready counters (one 128B line each)
__device__ unsigned g_cntu[(T + 1) * 32];    // u[t]-ready counters
__device__ float    g_kgate[K4];             // key lstm pre-activation gates

// ---------------- helpers ----------------
__device__ __forceinline__ float sigf(float x) {
    return __fdividef(1.f, 1.f + __expf(-x));
}
__device__ __forceinline__ float tanhf_(float x) {
    x = fminf(15.f, fmaxf(-15.f, x));
    float e = __expf(-2.f * x);
    return __fdividef(1.f - e, 1.f + e);
}
__device__ __forceinline__ float wsum(float v) {
#pragma unroll
    for (int o = 16; o > 0; o >>= 1) v += __shfl_xor_sync(0xffffffffu, v, o);
    return v;
}
__device__ __forceinline__ unsigned ld_acq(const unsigned* p) {
    unsigned v;
    asm volatile("ld.acquire.gpu.global.u32 %0, [%1];" : "=r"(v) : "l"(p) : "memory");
    return v;
}
__device__ __forceinline__ void red_rel(unsigned* p) {
    asm volatile("red.release.gpu.global.add.u32 [%0], %1;" :: "l"(p), "r"(1u) : "memory");
}
__device__ __forceinline__ uint32_t smem_u32(const void* p) {
    uint32_t a;
    asm("{ .reg .u64 t; cvta.to.shared.u64 t, %1; cvt.u32.u64 %0, t; }" : "=r"(a) : "l"(p));
    return a;
}
__device__ __forceinline__ uint32_t mapa_u32(uint32_t laddr, uint32_t rank) {
    uint32_t r;
    asm("mapa.shared::cluster.u32 %0, %1, %2;" : "=r"(r) : "r"(laddr), "r"(rank));
    return r;
}

// multi-value butterfly: 8 sums in 9 shfls; lane L ends with sum(a[L&7])
__device__ __forceinline__ float reduce8(const float* a, int lane) {
    float v01 = (lane & 1) ? a[1] : a[0];
    v01 += __shfl_xor_sync(0xffffffffu, (lane & 1) ? a[0] : a[1], 1);
    float v23 = (lane & 1) ? a[3] : a[2];
    v23 += __shfl_xor_sync(0xffffffffu, (lane & 1) ? a[2] : a[3], 1);
    float v45 = (lane & 1) ? a[5] : a[4];
    v45 += __shfl_xor_sync(0xffffffffu, (lane & 1) ? a[4] : a[5], 1);
    float v67 = (lane & 1) ? a[7] : a[6];
    v67 += __shfl_xor_sync(0xffffffffu, (lane & 1) ? a[6] : a[7], 1);
    float v03 = (lane & 2) ? v23 : v01;
    v03 += __shfl_xor_sync(0xffffffffu, (lane & 2) ? v01 : v23, 2);
    float v47 = (lane & 2) ? v67 : v45;
    v47 += __shfl_xor_sync(0xffffffffu, (lane & 2) ? v45 : v67, 2);
    float v = (lane & 4) ? v47 : v03;
    v += __shfl_xor_sync(0xffffffffu, (lane & 4) ? v03 : v47, 4);
    v += __shfl_xor_sync(0xffffffffu, v, 8);
    v += __shfl_xor_sync(0xffffffffu, v, 16);
    return v;
}
// pair butterfly: lane L ends with sum(a8 if L even else a9)
__device__ __forceinline__ float reduce2(float a8, float a9, int lane) {
    float x = (lane & 1) ? a9 : a8;
    x += __shfl_xor_sync(0xffffffffu, (lane & 1) ? a8 : a9, 1);
    x += __shfl_xor_sync(0xffffffffu, x, 2);
    x += __shfl_xor_sync(0xffffffffu, x, 4);
    x += __shfl_xor_sync(0xffffffffu, x, 8);
    x += __shfl_xor_sync(0xffffffffu, x, 16);
    return x;
}

// cluster-scope mbarrier ops
__device__ __forceinline__ void mbar_init(uint32_t addr, unsigned count) {
    asm volatile("mbarrier.init.shared.b64 [%0], %1;" :: "r"(addr), "r"(count) : "memory");
}
__device__ __forceinline__ void mbar_arrive_remote(uint32_t laddr, uint32_t peer) {
    uint32_t ra = mapa_u32(laddr, peer);
    asm volatile("mbarrier.arrive.release.cluster.shared::cluster.b64 _, [%0];"
                 :: "r"(ra) : "memory");
}
__device__ __forceinline__ void mbar_wait_cluster(uint32_t addr, uint32_t parity) {
    uint32_t done;
    asm volatile(
        "{\n\t.reg .pred p;\n\t"
        "mbarrier.try_wait.parity.acquire.cluster.shared::cta.b64 p, [%1], %2;\n\t"
        "selp.b32 %0, 1, 0, p;\n\t}"
        : "=r"(done) : "r"(addr), "r"(parity) : "memory");
    while (!done) {
        asm volatile(
            "{\n\t.reg .pred p;\n\t"
            "mbarrier.try_wait.parity.acquire.cluster.shared::cta.b64 p, [%1], %2, 0x989680;\n\t"
            "selp.b32 %0, 1, 0, p;\n\t}"
            : "=r"(done) : "r"(addr), "r"(parity) : "memory");
    }
}
__device__ __forceinline__ void st_cluster_b32(uint32_t ra, float v) {
    asm volatile("st.shared::cluster.b32 [%0], %1;" :: "r"(ra), "r"(__float_as_uint(v)) : "memory");
}

// ---------------- init: counters ----------------
__global__ void init_kernel() {
    int i = blockIdx.x * blockDim.x + threadIdx.x;
    if (i < (T + 1) * 32) {
        g_cnt0[i] = 0u;
        g_cntu[i] = 0u;
    }
    if (i < HID) { g_h0[i] = 0.f; g_h1[i] = 0.f; }
}

// ---------------- kernel A: xg0 = concat-embed @ Wih0^T + bih0 + bhh0 ----------------
__global__ void __launch_bounds__(256, 1) xg0_kernel(
    const int* __restrict__ xr, const int* __restrict__ xcpc, const int* __restrict__ xma,
    const float* __restrict__ em, const float* __restrict__ ec, const float* __restrict__ er,
    const float* __restrict__ Wih0, const float* __restrict__ bih0, const float* __restrict__ bhh0)
{
    __shared__ float xs[64][53];
    __shared__ float ws[160][53];
    const int bt0 = blockIdx.x * 64;
    const int br0 = blockIdx.y * 160;
    const int tid = threadIdx.x;
    float acc[8][5];
#pragma unroll
    for (int i = 0; i < 8; i++)
#pragma unroll
        for (int r = 0; r < 5; r++) acc[i][r] = 0.f;

    for (int ch = 0; ch < 3; ch++) {
        const float* tab = (ch == 0) ? em : ((ch == 1) ? ec : er);
        const int* idx = (ch == 0) ? xma : ((ch == 1) ? xcpc : xr);
        for (int i = tid; i < 64 * 50; i += 256) {
            int tt = i / 50, kk = i - tt * 50;
            xs[tt][kk] = tab[idx[bt0 + tt] * EMB + kk];
        }
        for (int i = tid; i < 160 * 50; i += 256) {
            int rr = i / 50, kk = i - rr * 50;
            ws[rr][kk] = Wih0[(br0 + rr) * E3 + ch * 50 + kk];
        }
        __syncthreads();
        const int tr = tid & 31, tc = tid >> 5;
#pragma unroll 5
        for (int kk = 0; kk < 50; kk++) {
            float a[8], wv[5];
#pragma unroll
            for (int i = 0; i < 8; i++) a[i] = xs[tc * 8 + i][kk];
#pragma unroll
            for (int r = 0; r < 5; r++) wv[r] = ws[tr * 5 + r][kk];
#pragma unroll
            for (int i = 0; i < 8; i++)
#pragma unroll
                for (int r = 0; r < 5; r++) acc[i][r] = fmaf(a[i], wv[r], acc[i][r]);
        }
        __syncthreads();
    }
    const int tr = tid & 31, tc = tid >> 5;
#pragma unroll
    for (int r = 0; r < 5; r++) {
        int rg = br0 + tr * 5 + r;
        float bias = bih0[rg] + bhh0[rg];
#pragma unroll
        for (int i = 0; i < 8; i++) {
            int t = bt0 + tc * 8 + i;
            g_xg0[(size_t)t * G4 + rg] = acc[i][r] + bias;
        }
    }
}

// ---------------- kernel B: persistent recurrence with DSMEM clusters ----------------
// grid = 48 CTAs, cluster dim 16:
//   cluster 0 (blocks  0-15): layer0 recurrence, h handoff via DSMEM scalar stores +
//     per-peer mbarrier arrive.release; publishes h0 to global for helpers.
//   cluster 1 (blocks 16-31): layer1 recurrence, same shape; consumes u[t] via cntu.
//   cluster 2 (blocks 32-47): helpers: u[t] = Wih1*h0[t] + biases (global counter path).
__global__ void __launch_bounds__(THREADS, 1) lstm_main_kernel(
    const float* __restrict__ Whh0,
    const float* __restrict__ Wih1,
    const float* __restrict__ Whh1,
    const float* __restrict__ bih1,
    const float* __restrict__ bhh1)
{
    const int tid  = threadIdx.x;
    const int warp = tid >> 5;
    const int lane = tid & 31;
    const int role = blockIdx.x >> 4;    // 0=L0, 1=L1, 2=helpers
    const int rank = blockIdx.x & 15;

    if (role == 2) {
        // ---------------- helpers: u[t] = Wih1 * h0[t] + (bih1+bhh1) ----------------
        float w[RPW][13];
#pragma unroll
        for (int r = 0; r < RPW; r++) {
            int f = warp * RPW + r;
            int row = (f & 3) * 400 + rank * CELLS + (f >> 2);
#pragma unroll
            for (int c = 0; c < 13; c++) {
                int k = lane + 32 * c;
                w[r][c] = (k < HID) ? Wih1[(size_t)row * HID + k] : 0.f;
            }
        }
        float bias = 0.f;
        int doff = 0;
        if (lane < RPW) {
            int f = warp * RPW + lane;
            int cell = rank * CELLS + (f >> 2);
            bias = bih1[(f & 3) * 400 + cell] + bhh1[(f & 3) * 400 + cell];
            doff = (f & 3) * 400 + cell;
        }
        for (int t = 0; t < T; t++) {
            const unsigned* cp = g_cnt0 + (size_t)(t + 1) * 32;   // h0[t] in slot t+1
            while (ld_acq(cp) < CL) {}
            const float* hb = g_h0 + (size_t)(t + 1) * HID;
            float hv[13];
#pragma unroll
            for (int c = 0; c < 13; c++) {
                int k = lane + 32 * c;
                hv[c] = (k < HID) ? __ldcg(hb + k) : 0.f;
            }
            float a[RPW];
#pragma unroll
            for (int r = 0; r < RPW; r++) a[r] = 0.f;
#pragma unroll
            for (int c = 0; c < 13; c++)
#pragma unroll
                for (int r = 0; r < RPW; r++) a[r] = fmaf(w[r][c], hv[c], a[r]);
            float v  = reduce8(a, lane);
            float v2 = reduce2(a[8], a[9], lane);
            if (lane < RPW) {
                float val = (lane < 8) ? v : v2;
                __stcg(g_u + (size_t)t * G4 + doff, val + bias);
            }
            __syncthreads();
            if (tid == 0) red_rel(g_cntu + (size_t)t * 32);
        }
        return;
    }

    // ---------------- recurrence clusters (L0 / L1) ----------------
    __shared__ __align__(16) float hbuf[2][HIDP];
    __shared__ __align__(16) float gsum[ROWS];
    __shared__ __align__(16) float hstage[28];
    __shared__ __align__(8)  unsigned long long mbar;

    const float* Whh = (role == 0) ? Whh0 : Whh1;
    float* ghout     = (role == 0) ? g_h0 : g_h1;

    float w[RPW][13];
#pragma unroll
    for (int r = 0; r < RPW; r++) {
        int f = warp * RPW + r;
        int row = (f & 3) * 400 + rank * CELLS + (f >> 2);
#pragma unroll
        for (int c = 0; c < 13; c++) {
            int k = lane + 32 * c;
            w[r][c] = (k < HID) ? Whh[(size_t)row * HID + k] : 0.f;
        }
    }
    const uint32_t hbuf_a = smem_u32(&hbuf[0][0]);
    const uint32_t mbar_a = smem_u32(&mbar);

    // init: zero both h buffers (pads stay zero forever), init mbarrier
    for (int i = tid; i < 2 * HIDP; i += THREADS) ((float*)hbuf)[i] = 0.f;
    if (tid == 0) mbar_init(mbar_a, CL);
    __syncthreads();
    asm volatile("barrier.cluster.arrive.aligned;" ::: "memory");
    asm volatile("barrier.cluster.wait.aligned;" ::: "memory");

    float cst = 0.f;
    for (int t = 0; t < T; t++) {
        // warp0 prefetch of per-cell input gates (independent of h -> before wait)
        float x0 = 0.f, x1 = 0.f, x2 = 0.f, x3 = 0.f;
        if (warp == 0 && lane < CELLS) {
            int cell = rank * CELLS + lane;
            if (role == 0) {
                const float* xg = g_xg0 + (size_t)t * G4 + cell;
                x0 = __ldg(xg); x1 = __ldg(xg + 400); x2 = __ldg(xg + 800); x3 = __ldg(xg + 1200);
            } else {
                const unsigned* cu = g_cntu + (size_t)t * 32;
                while (ld_acq(cu) < CL) {}
                const float* up = g_u + (size_t)t * G4 + cell;
                x0 = __ldcg(up);       x1 = __ldcg(up + 400);
                x2 = __ldcg(up + 800); x3 = __ldcg(up + 1200);
            }
        }
        // wait for h[t] (phase t-1); step 0 reads the zero-initialized buffer
        if (t > 0) mbar_wait_cluster(mbar_a, (unsigned)((t - 1) & 1));

        const float* hb = &hbuf[t & 1][0];
        float hv[13];
#pragma unroll
        for (int c = 0; c < 13; c++) hv[c] = hb[lane + 32 * c];   // pads are zero
        float a[RPW];
#pragma unroll
        for (int r = 0; r < RPW; r++) a[r] = 0.f;
#pragma unroll
        for (int c = 0; c < 13; c++)
#pragma unroll
            for (int r = 0; r < RPW; r++) a[r] = fmaf(w[r][c], hv[c], a[r]);
        float v  = reduce8(a, lane);
        float v2 = reduce2(a[8], a[9], lane);
        if (lane < RPW) gsum[warp * RPW + lane] = (lane < 8) ? v : v2;
        __syncthreads();

        if (warp == 0) {
            if (lane < CELLS) {
                float4 gv = *((const float4*)gsum + lane);   // [i,f,g,o] for this cell
                float gi = sigf(gv.x + x0);
                float gf = sigf(gv.y + x1);
                float gg = tanhf_(gv.z + x2);
                float go = sigf(gv.w + x3);
                cst = gf * cst + gi * gg;
                float h = go * tanhf_(cst);
                hstage[lane] = h;
                __stcg(ghout + (size_t)(t + 1) * HID + rank * CELLS + lane, h);
            }
            __syncwarp();
            if (lane < CL) {
                // copy this CTA's 25-float slice into peer `lane`'s next h buffer
                // scalar b32 cluster stores: 4B alignment only (v4 would need 16B,
                // but slice base rank*100 bytes is not 16B-aligned)
                float s[CELLS];
#pragma unroll
                for (int q = 0; q < CELLS; q++) s[q] = hstage[q];
                uint32_t dst = mapa_u32(
                    hbuf_a + (uint32_t)(((t + 1) & 1) * HIDP + rank * CELLS) * 4u,
                    (uint32_t)lane);
#pragma unroll
                for (int q = 0; q < CELLS; q++) st_cluster_b32(dst + 4u * q, s[q]);
                mbar_arrive_remote(mbar_a, (uint32_t)lane);   // release: orders this lane's writes
            }
            __syncwarp();
            if (role == 0 && lane == 0) red_rel(g_cnt0 + (size_t)(t + 1) * 32);
        }
    }
    // final cluster barrier: no CTA exits while peers may still write its smem
    asm volatile("barrier.cluster.arrive.aligned;" ::: "memory");
    asm volatile("barrier.cluster.wait.aligned;" ::: "memory");
}

// ---------------- kernel C: rtoken = rnn_out @ fcW^T + fcb ----------------
__global__ void __launch_bounds__(256, 1) rtoken_kernel(
    const float* __restrict__ fcW, const float* __restrict__ fcb, float* __restrict__ out)
{
    __shared__ float xs[64][53];
    __shared__ float ws[160][53];
    const int bt0 = blockIdx.x * 64;
    const int tid = threadIdx.x;
    float acc[8][5];
#pragma unroll
    for (int i = 0; i < 8; i++)
#pragma unroll
        for (int r = 0; r < 5; r++) acc[i][r] = 0.f;

    for (int ch = 0; ch < 8; ch++) {
        int k0 = ch * 50;
        for (int i = tid; i < 64 * 50; i += 256) {
            int tt = i / 50, kk = i - tt * 50;
            xs[tt][kk] = g_h1[(size_t)(bt0 + tt + 1) * HID + k0 + kk];
        }
        for (int i = tid; i < 160 * 50; i += 256) {
            int rr = i / 50, kk = i - rr * 50;
            ws[rr][kk] = (rr < E3) ? fcW[rr * HID + k0 + kk] : 0.f;
        }
        __syncthreads();
        const int tr = tid & 31, tc = tid >> 5;
#pragma unroll 5
        for (int kk = 0; kk < 50; kk++) {
            float a[8], wv[5];
#pragma unroll
            for (int i = 0; i < 8; i++) a[i] = xs[tc * 8 + i][kk];
#pragma unroll
            for (int r = 0; r < 5; r++) wv[r] = ws[tr * 5 + r][kk];
#pragma unroll
            for (int i = 0; i < 8; i++)
#pragma unroll
                for (int r = 0; r < 5; r++) acc[i][r] = fmaf(a[i], wv[r], acc[i][r]);
        }
        __syncthreads();
    }
    const int tr = tid & 31, tc = tid >> 5;
#pragma unroll
    for (int r = 0; r < 5; r++) {
        int rg = tr * 5 + r;
        if (rg < E3) {
            float bias = fcb[rg];
#pragma unroll
            for (int i = 0; i < 8; i++) {
                int t = bt0 + tc * 8 + i;
                out[(size_t)t * E3 + rg] = acc[i][r] + bias;
            }
        }
    }
}

// ---------------- kernel D: context fill ----------------
__global__ void __launch_bounds__(128, 1) ctx_kernel(
    const float* __restrict__ actW, const float* __restrict__ actb,
    const float* __restrict__ Dp, float* __restrict__ out)
{
    const int t = blockIdx.x;
    const int warp = threadIdx.x >> 5, lane = threadIdx.x & 31;
    __shared__ float red[4];
    const float* hr = g_h1 + (size_t)(t + 1) * HID;
    const float* wrow = (warp < 3) ? (actW + warp * HID) : Dp;
    float acc = 0.f;
#pragma unroll
    for (int c = 0; c < 13; c++) {
        int k = lane + 32 * c;
        if (k < HID) acc = fmaf(__ldg(wrow + k), __ldg(hr + k), acc);
    }
    acc = wsum(acc);
    if (lane == 0) red[warp] = acc + ((warp < 3) ? actb[warp] : 0.f);
    __syncthreads();
    float l0 = red[0], l1 = red[1], l2 = red[2], d = red[3];
    float m = fmaxf(l0, fmaxf(l1, l2));
    float e0 = __expf(l0 - m), e1 = __expf(l1 - m), e2 = __expf(l2 - m);
    float p0 = __fdividef(e0, e0 + e1 + e2);
    float v = p0 * sigf(d);

    float4* dst = (float4*)(out + OFF_CTX + (size_t)t * 32 * HID);
    float4 vz = make_float4(v, v, v, v);
    float4 z = make_float4(0.f, 0.f, 0.f, 0.f);
    for (int q = threadIdx.x; q < 3200; q += 128) {
        __stcs(dst + q, (q < 100) ? vz : z);
    }
}

// ---------------- kernel E1: key lstm gates ----------------
__global__ void __launch_bounds__(128, 1) keygate_kernel(
    const float* __restrict__ kWih, const float* __restrict__ kbih, const float* __restrict__ kbhh)
{
    const int gw = blockIdx.x * 4 + (threadIdx.x >> 5);
    const int lane = threadIdx.x & 31;
    const float* hr = g_h1 + (size_t)T * HID;
    float hv[13];
#pragma unroll
    for (int c = 0; c < 13; c++) {
        int k = lane + 32 * c;
        hv[c] = (k < HID) ? __ldg(hr + k) : 0.f;
    }
    for (int rr = 0; rr < 30; rr++) {
        int r = gw * 30 + rr;
        float acc = 0.f;
#pragma unroll
        for (int c = 0; c < 13; c++) {
            int k = lane + 32 * c;
            if (k < HID) acc = fmaf(__ldg(kWih + (size_t)r * HID + k), hv[c], acc);
        }
        acc = wsum(acc);
        if (lane == 0) g_kgate[r] = acc + kbih[r] + kbhh[r];
    }
}

// ---------------- kernel E2: kh nonlinearity + ktoken ----------------
__global__ void __launch_bounds__(512, 1) keyout_kernel(
    const float* __restrict__ kfcW, const float* __restrict__ kfcb, float* __restrict__ out)
{
    __shared__ float kh[KEY];
    const int tid = threadIdx.x;
    if (tid < KEY) {
        float gi = g_kgate[tid], gg = g_kgate[600 + tid], go = g_kgate[900 + tid];
        float c = sigf(gi) * tanhf_(gg);
        kh[tid] = sigf(go) * tanhf_(c);
    }
    __syncthreads();
    const int warp = tid >> 5, lane = tid & 31;
    for (int rr = 0; rr < 25; rr++) {
        int r = warp * 25 + rr;
        float acc = 0.f;
#pragma unroll
        for (int c = 0; c < 10; c++) {
            int k = lane + 32 * c;
            if (k < KEY) acc = fmaf(__ldg(kfcW + (size_t)r * KEY + k), kh[k], acc);
        }
        acc = wsum(acc);
        if (lane == 0) out[OFF_KTOK + r] = acc + kfcb[r];
    }
}

// ---------------- launch ----------------
extern "C" void kernel_launch(void* const* d_in, const int* in_sizes, int n_in,
                              void* d_out, int out_size)
{
    const int*   xr       = (const int*)d_in[0];
    const int*   xcpc     = (const int*)d_in[1];
    const int*   xma      = (const int*)d_in[2];
    const float* em       = (const float*)d_in[3];
    const float* ec       = (const float*)d_in[4];
    const float* er       = (const float*)d_in[5];
    const float* Wih0     = (const float*)d_in[6];
    const float* Whh0     = (const float*)d_in[7];
    const float* bih0     = (const float*)d_in[8];
    const float* bhh0     = (const float*)d_in[9];
    const float* Wih1     = (const float*)d_in[10];
    const float* Whh1     = (const float*)d_in[11];
    const float* bih1     = (const float*)d_in[12];
    const float* bhh1     = (const float*)d_in[13];
    const float* fcW      = (const float*)d_in[14];
    const float* fcb      = (const float*)d_in[15];
    const float* actW     = (const float*)d_in[16];
    const float* actb     = (const float*)d_in[17];
    const float* Dp       = (const float*)d_in[18];
    const float* kWih     = (const float*)d_in[19];
    const float* kbih     = (const float*)d_in[21];
    const float* kbhh     = (const float*)d_in[22];
    const float* kfcW     = (const float*)d_in[23];
    const float* kfcb     = (const float*)d_in[24];
    float* out = (float*)d_out;

    init_kernel<<<((T + 1) * 32 + 255) / 256, 256>>>();
    xg0_kernel<<<dim3(T / 64, G4 / 160), 256>>>(xr, xcpc, xma, em, ec, er, Wih0, bih0, bhh0);

    // 16-CTA clusters (non-portable size): 3 clusters = L0 / L1 / helpers
    cudaFuncSetAttribute(lstm_main_kernel,
                         cudaFuncAttributeNonPortableClusterSizeAllowed, 1);
    cudaLaunchConfig_t cfg = {};
    cfg.gridDim = {48, 1, 1};
    cfg.blockDim = {THREADS, 1, 1};
    cfg.dynamicSmemBytes = 0;
    cfg.stream = 0;
    cudaLaunchAttribute attrs[1];
    attrs[0].id = cudaLaunchAttributeClusterDimension;
    attrs[0].val.clusterDim = {CL, 1, 1};
    cfg.attrs = attrs;
    cfg.numAttrs = 1;
    cudaLaunchKernelEx(&cfg, lstm_main_kernel, Whh0, Wih1, Whh1, bih1, bhh1);

    rtoken_kernel<<<T / 64, 256>>>(fcW, fcb, out);
    ctx_kernel<<<T, 128>>>(actW, actb, Dp, out);
    keygate_kernel<<<10, 128>>>(kWih, kbih, kbhh);
    keyout_kernel<<<1, 512>>>(kfcW, kfcb, out);
}